// round 16
// baseline (speedup 1.0000x reference)
#include <cuda_runtime.h>
#include <cooperative_groups.h>
#include <cstdint>

namespace cg = cooperative_groups;
using u64 = unsigned long long;
using u32 = unsigned int;

// Problem constants
constexpr int B = 32;
constexpr int N = 131072;
constexpr int K = 1024;

// Config: one 8-CTA cluster serves TWO batches
constexpr int C     = 8;        // CTAs per cluster
constexpr int Q     = 2;        // batches per cluster
constexpr int PAIRS = B / Q;    // 16 clusters
constexpr int T     = 1024;     // threads per CTA (32 warps)
constexpr int W     = T / 32;
constexpr int S     = N / C;    // 16384 pts per CTA per batch
constexpr int CH    = 128;      // points per chunk
constexpr int NCH   = S / CH;   // 128 chunks per CTA per batch
constexpr int CELLS = 4096;     // 16^3 Morton cells per batch

// Static device scratch (allocation-free): sorted SoA
__device__ __align__(16) float g_x[B * N];
__device__ __align__(16) float g_y[B * N];
__device__ __align__(16) float g_z[B * N];
__device__ __align__(16) int   g_i[B * N];   // original within-batch index

// ---- Morton cell id (4 bits/dim) ----
__device__ __forceinline__ u32 expand3_4(u32 v) {
    return (v & 1u) | ((v & 2u) << 2) | ((v & 4u) << 4) | ((v & 8u) << 6);
}
__device__ __forceinline__ int cell_of(float x, float y, float z) {
    int ix = min(15, max(0, (int)((x + 4.5f) * (16.0f / 9.0f))));
    int iy = min(15, max(0, (int)((y + 4.5f) * (16.0f / 9.0f))));
    int iz = min(15, max(0, (int)((z + 4.5f) * (16.0f / 9.0f))));
    return (int)(expand3_4((u32)ix) | (expand3_4((u32)iy) << 1) |
                 (expand3_4((u32)iz) << 2));
}

struct __align__(32) Slot {
    u32 lo, hi;        // packed best: (dist_bits<<32) | ~origidx
    float x, y, z;
    float pad0, pad1, pad2;
};

// SMEM layout (bytes) — dist region doubles as sort scratch in the prologue
constexpr int SM_DIST = 0;                          // Q*S floats = 131072
constexpr int SM_BOX  = SM_DIST + Q * S * 4;        // Q*NCH*6 f  =   6144
constexpr int SM_CB   = SM_BOX + Q * NCH * 24;      // Q*NCH u64  =   2048
constexpr int SM_CX   = SM_CB + Q * NCH * 8;        // Q*NCH f
constexpr int SM_CY   = SM_CX + Q * NCH * 4;
constexpr int SM_CZ   = SM_CY + Q * NCH * 4;
constexpr int SM_WL   = SM_CZ + Q * NCH * 4;        // Q*NCH u32 worklist
constexpr int SM_WC   = SM_WL + Q * NCH * 4;        // 2 u32 + pad
constexpr int SM_SL   = SM_WC + 16;                 // Slot[2][Q][C] = 1024
constexpr int SMEM_TOTAL = SM_SL + 2 * Q * C * 32;  // ~144.6 KB

__global__ void __cluster_dims__(C, 1, 1) __launch_bounds__(T, 1)
fps_kernel(const float* __restrict__ pts, const int* __restrict__ init_idx,
           float* __restrict__ out)
{
    extern __shared__ char smem[];
    float4* sd4  = (float4*)(smem + SM_DIST);   // [Q*4096] float4
    float*  sbox = (float*)(smem + SM_BOX);     // [Q*NCH*6]
    u64*    scb  = (u64*)(smem + SM_CB);        // [Q*NCH]
    float*  scx  = (float*)(smem + SM_CX);
    float*  scy  = (float*)(smem + SM_CY);
    float*  scz  = (float*)(smem + SM_CZ);
    u32*    swl  = (u32*)(smem + SM_WL);        // [Q*NCH]
    u32*    swc  = (u32*)(smem + SM_WC);
    Slot*   sl   = (Slot*)(smem + SM_SL);       // [2][Q][C]

    // sort scratch overlays the dist region (freed before dist init)
    u32* PH = (u32*)(smem + SM_DIST);           // [Q][CELLS] local hist
    u32* PC = PH + Q * CELLS;                   // [Q][CELLS] counters
    int* PW = (int*)(PC + Q * CELLS);           // [32] scan temps

    cg::cluster_group cluster = cg::this_cluster();
    const int rank = blockIdx.x;                // 0..7
    const int pair = blockIdx.y;                // 0..15
    const int t    = threadIdx.x;
    const int warp = t >> 5, lane = t & 31;

    int bOff[Q], gb4[Q];                        // batch offset; float4 slice base
    #pragma unroll
    for (int q = 0; q < Q; q++) {
        bOff[q] = (pair * Q + q) * N;
        gb4[q]  = (bOff[q] + rank * S) >> 2;
    }
    const float4* __restrict__ gx4 = (const float4*)g_x;
    const float4* __restrict__ gy4 = (const float4*)g_y;
    const float4* __restrict__ gz4 = (const float4*)g_z;
    const int4*   __restrict__ gi4 = (const int4*)g_i;

    // ======================= in-kernel preprocessing =======================
    #pragma unroll
    for (int j = 0; j < Q * CELLS / T; j++) PH[t + j * T] = 0;
    __syncthreads();
    #pragma unroll
    for (int q = 0; q < Q; q++) {
        int base = bOff[q] + rank * S;
        for (int i = t; i < S; i += T) {
            int gi = base + i;
            float x = pts[3 * gi], y = pts[3 * gi + 1], z = pts[3 * gi + 2];
            atomicAdd(&PH[q * CELLS + cell_of(x, y, z)], 1u);
        }
    }
    __syncthreads();
    cluster.sync();   // peers' hists complete

    // combine peer hists (DSMEM) + exclusive scan -> per-CTA base counters
    #pragma unroll
    for (int q = 0; q < Q; q++) {
        int v[4], mb[4];
        #pragma unroll
        for (int j = 0; j < 4; j++) {
            int cell = q * CELLS + t * 4 + j;
            int tot = 0, base = 0;
            #pragma unroll
            for (int r = 0; r < C; r++) {
                u32* hp = (u32*)cluster.map_shared_rank(PH + cell, r);
                int h = (int)*hp;
                if (r < rank) base += h;
                tot += h;
            }
            v[j] = tot; mb[j] = base;
        }
        int s = v[0] + v[1] + v[2] + v[3];
        int ps = s;
        #pragma unroll
        for (int o = 1; o < 32; o <<= 1) {
            int u = __shfl_up_sync(0xffffffffu, ps, o);
            if (lane >= o) ps += u;
        }
        if (lane == 31) PW[warp] = ps;
        __syncthreads();
        if (warp == 0) {
            int x = PW[lane];
            #pragma unroll
            for (int o = 1; o < 32; o <<= 1) {
                int u = __shfl_up_sync(0xffffffffu, x, o);
                if (lane >= o) x += u;
            }
            PW[lane] = x;
        }
        __syncthreads();
        int run = (warp > 0 ? PW[warp - 1] : 0) + (ps - s);
        #pragma unroll
        for (int j = 0; j < 4; j++) {
            PC[q * CELLS + t * 4 + j] = (u32)(run + mb[j]);
            run += v[j];
        }
        __syncthreads();
    }

    // scatter into batch-sorted SoA
    #pragma unroll
    for (int q = 0; q < Q; q++) {
        int base = bOff[q] + rank * S;
        for (int i = t; i < S; i += T) {
            int gi = base + i;
            float x = pts[3 * gi], y = pts[3 * gi + 1], z = pts[3 * gi + 2];
            int cell = cell_of(x, y, z);
            int pos = (int)atomicAdd(&PC[q * CELLS + cell], 1u);
            int o = bOff[q] + pos;
            g_x[o] = x; g_y[o] = y; g_z[o] = z; g_i[o] = gi - bOff[q];
        }
    }
    __threadfence();
    __syncthreads();
    cluster.sync();   // all points of both batches sorted & visible

    // per-chunk bboxes into SMEM (one warp per chunk; Q*NCH = 256 chunks)
    for (int cc = warp; cc < Q * NCH; cc += W) {
        int q = cc >> 7, c = cc & (NCH - 1);
        int f = gb4[q] + c * 32 + lane;
        float4 X = gx4[f], Yv4 = gy4[f], Z = gz4[f];
        float mnx = fminf(fminf(X.x, X.y), fminf(X.z, X.w));
        float mxx = fmaxf(fmaxf(X.x, X.y), fmaxf(X.z, X.w));
        float mny = fminf(fminf(Yv4.x, Yv4.y), fminf(Yv4.z, Yv4.w));
        float mxy = fmaxf(fmaxf(Yv4.x, Yv4.y), fmaxf(Yv4.z, Yv4.w));
        float mnz = fminf(fminf(Z.x, Z.y), fminf(Z.z, Z.w));
        float mxz = fmaxf(fmaxf(Z.x, Z.y), fmaxf(Z.z, Z.w));
        #pragma unroll
        for (int s2 = 16; s2 > 0; s2 >>= 1) {
            mnx = fminf(mnx, __shfl_xor_sync(0xffffffffu, mnx, s2));
            mxx = fmaxf(mxx, __shfl_xor_sync(0xffffffffu, mxx, s2));
            mny = fminf(mny, __shfl_xor_sync(0xffffffffu, mny, s2));
            mxy = fmaxf(mxy, __shfl_xor_sync(0xffffffffu, mxy, s2));
            mnz = fminf(mnz, __shfl_xor_sync(0xffffffffu, mnz, s2));
            mxz = fmaxf(mxz, __shfl_xor_sync(0xffffffffu, mxz, s2));
        }
        if (lane == 0) {
            float* bb = &sbox[cc * 6];
            bb[0] = mnx; bb[1] = mxx; bb[2] = mny;
            bb[3] = mxy; bb[4] = mnz; bb[5] = mxz;
        }
    }
    __syncthreads();

    // dist init (overwrites sort scratch) + chunk state + first points
    #pragma unroll
    for (int j = 0; j < Q * S / (4 * T); j++)
        sd4[t + j * T] = make_float4(1e10f, 1e10f, 1e10f, 1e10f);
    if (t < Q * NCH) {
        scb[t] = ((u64)__float_as_uint(1e10f)) << 32;   // forces touch at k=1
        scx[t] = 0.f; scy[t] = 0.f; scz[t] = 0.f;
    }
    if (t == 0) { swc[0] = 0; swc[1] = 0; }

    float lx[Q], ly[Q], lz[Q];
    #pragma unroll
    for (int q = 0; q < Q; q++) {
        int idx0 = init_idx[pair * Q + q];
        lx[q] = pts[3 * (bOff[q] + idx0) + 0];
        ly[q] = pts[3 * (bOff[q] + idx0) + 1];
        lz[q] = pts[3 * (bOff[q] + idx0) + 2];
        if (rank == 0 && t == 0) {
            out[((pair * Q + q) * K + 0) * 3 + 0] = lx[q];
            out[((pair * Q + q) * K + 0) * 3 + 1] = ly[q];
            out[((pair * Q + q) * K + 0) * 3 + 2] = lz[q];
        }
    }
    __syncthreads();

    // ======================= K-1 sequential iterations ======================
    for (int k = 1; k < K; k++) {
        const int ph = k & 1;

        // phase A: threads 0..255 bound-check all chunks of both batches
        if (t == 0) swc[ph ^ 1] = 0;
        if (t < Q * NCH) {
            int q = t >> 7;
            const float* bb = &sbox[t * 6];
            float dx = fmaxf(0.0f, fmaxf(bb[0] - lx[q], lx[q] - bb[1]));
            float dy = fmaxf(0.0f, fmaxf(bb[2] - ly[q], ly[q] - bb[3]));
            float dz = fmaxf(0.0f, fmaxf(bb[4] - lz[q], lz[q] - bb[5]));
            float lb2 = __fmaf_rn(dx, dx, __fmaf_rn(dy, dy, dz * dz));
            float cub = __uint_as_float((u32)(scb[t] >> 32));
            if (lb2 * 0.99999f < cub) {             // conservative margin
                u32 p = atomicAdd(&swc[ph], 1u);
                swl[p] = (u32)t;                    // encodes (q,c)
            }
        }
        __syncthreads();
        const int nw = (int)swc[ph];

        // phase B: warps drain the combined worklist (both batches interleave)
        for (int wi = warp; wi < nw; wi += W) {
            int code = (int)swl[wi];
            int q = code >> 7, c = code & (NCH - 1);
            int f = gb4[q] + c * 32 + lane;
            float4 X = gx4[f];
            float4 Yv4 = gy4[f];
            float4 Z = gz4[f];
            int4   I = gi4[f];
            float4 D = sd4[(code << 5) + lane];     // q*4096 + c*32 + lane
            const float* Xv = (const float*)&X;
            const float* Yv = (const float*)&Yv4;
            const float* Zv = (const float*)&Z;
            const int*   Iv = (const int*)&I;
            float* Dv = (float*)&D;
            u64 bk = 0ULL;
            float bx = 0.f, by = 0.f, bz = 0.f;
            #pragma unroll
            for (int ccx = 0; ccx < 4; ccx++) {
                float dx = Xv[ccx] - lx[q], dy = Yv[ccx] - ly[q], dz = Zv[ccx] - lz[q];
                float d2 = __fmaf_rn(dx, dx, __fmaf_rn(dy, dy, dz * dz));
                float nd = fminf(Dv[ccx], d2);
                Dv[ccx] = nd;
                u64 key = (((u64)__float_as_uint(nd)) << 32) |
                          (u32)(~(u32)Iv[ccx]);
                if (key > bk) { bk = key; bx = Xv[ccx]; by = Yv[ccx]; bz = Zv[ccx]; }
            }
            sd4[(code << 5) + lane] = D;
            #pragma unroll
            for (int o = 16; o > 0; o >>= 1) {
                u64   ok = __shfl_xor_sync(0xffffffffu, bk, o);
                float ox = __shfl_xor_sync(0xffffffffu, bx, o);
                float oy = __shfl_xor_sync(0xffffffffu, by, o);
                float oz = __shfl_xor_sync(0xffffffffu, bz, o);
                if (ok > bk) { bk = ok; bx = ox; by = oy; bz = oz; }
            }
            if (lane == 0) {
                scb[code] = bk;
                scx[code] = bx; scy[code] = by; scz[code] = bz;
            }
        }
        __syncthreads();

        // phase C: warp q scans batch q's 128 keys; lanes 0..7 push in parallel
        if (warp < Q) {
            const int q = warp;
            u64 bk = 0ULL; int bc = 0;
            #pragma unroll
            for (int i = 0; i < NCH / 32; i++) {
                int c = q * NCH + lane + 32 * i;
                u64 e = scb[c];
                if (e > bk) { bk = e; bc = c; }
            }
            #pragma unroll
            for (int o = 16; o > 0; o >>= 1) {
                u64 ok = __shfl_xor_sync(0xffffffffu, bk, o);
                int oc = __shfl_xor_sync(0xffffffffu, bc, o);
                if (ok > bk) { bk = ok; bc = oc; }
            }
            // all lanes hold the batch winner; coords via broadcast LDS
            float px = scx[bc], py = scy[bc], pz = scz[bc];
            if (lane < C) {      // one lane per destination rank
                Slot* my = &sl[(ph * Q + q) * C + rank];
                Slot* p  = (Slot*)cluster.map_shared_rank(my, lane);
                uint4 w = make_uint4((u32)(bk & 0xffffffffull),
                                     (u32)(bk >> 32),
                                     __float_as_uint(px),
                                     __float_as_uint(py));
                *(uint4*)p = w;
                p->z = pz;
            }
        }

        cluster.sync();   // HW-sleep barrier; orders remote slot stores

        // every thread picks both batches' winners from local slots
        #pragma unroll
        for (int q = 0; q < Q; q++) {
            u64 gbk = 0ULL;
            float nx = 0.f, ny = 0.f, nz = 0.f;
            #pragma unroll
            for (int r = 0; r < C; r++) {
                const Slot* p = &sl[(ph * Q + q) * C + r];
                uint4 w = *(const uint4*)p;
                float z = p->z;
                u64 v = ((u64)w.y << 32) | w.x;
                if (v > gbk) {
                    gbk = v;
                    nx = __uint_as_float(w.z);
                    ny = __uint_as_float(w.w);
                    nz = z;
                }
            }
            lx[q] = nx; ly[q] = ny; lz[q] = nz;
            if (rank == 0 && t == 0) {
                out[((pair * Q + q) * K + k) * 3 + 0] = nx;
                out[((pair * Q + q) * K + k) * 3 + 1] = ny;
                out[((pair * Q + q) * K + k) * 3 + 2] = nz;
            }
        }
    }

    cluster.sync();   // keep SMEM alive until all peer traffic retired
}

extern "C" void kernel_launch(void* const* d_in, const int* in_sizes, int n_in,
                              void* d_out, int out_size) {
    const float* pts  = (const float*)d_in[0];
    const int*   init = (const int*)d_in[1];
    float*       out  = (float*)d_out;

    cudaFuncSetAttribute(fps_kernel,
                         cudaFuncAttributeMaxDynamicSharedMemorySize, SMEM_TOTAL);

    dim3 grid(C, PAIRS, 1);
    fps_kernel<<<grid, T, SMEM_TOTAL>>>(pts, init, out);
}